// round 16
// baseline (speedup 1.0000x reference)
#include <cuda_runtime.h>
#include <cstdint>

// Problem constants
// B=32, L=512, E=H=512, G=4H=2048, N=2 layers, V=32000
#define NB 32
#define NL 512
#define NH 512
#define NG 2048
#define NLAYERS 2

// Scratch (static device globals -- allocation-free).
// h rings padded +64 floats: the k-loop register pipeline prefetches one
// iteration past the slice end (value unused, must not fault).
__device__ float g_xg[(size_t)NL * NB * NG];   // (L*B, 4H) layer-0 gate preacts (input part + bias)
__device__ float g_h0[2 * NH * NB + 64];       // double-buffered h layer0, [buf][j][b]
__device__ float g_h1[2 * NH * NB + 64];       // double-buffered h layer1, [buf][j][b]
__device__ int   g_bar;                        // global barrier counter

// ---------------------------------------------------------------------------
// Packed f32x2 helpers (fma.rn.f32x2 -- 2 fp32 MACs per instruction)
// ---------------------------------------------------------------------------
__device__ __forceinline__ unsigned long long ffma2(unsigned long long a,
                                                    unsigned long long b,
                                                    unsigned long long c) {
    unsigned long long d;
    asm("fma.rn.f32x2 %0, %1, %2, %3;" : "=l"(d) : "l"(a), "l"(b), "l"(c));
    return d;
}
__device__ __forceinline__ unsigned long long addf2(unsigned long long a,
                                                    unsigned long long b) {
    unsigned long long d;
    asm("add.rn.f32x2 %0, %1, %2;" : "=l"(d) : "l"(a), "l"(b));
    return d;
}
__device__ __forceinline__ unsigned long long pack2(float x) {
    unsigned long long d;
    asm("mov.b64 %0, {%1, %1};" : "=l"(d) : "f"(x));
    return d;
}
__device__ __forceinline__ float2 unpack2(unsigned long long u) {
    float2 f;
    asm("mov.b64 {%0, %1}, %2;" : "=f"(f.x), "=f"(f.y) : "l"(u));
    return f;
}

__device__ __forceinline__ float rcp_fast(float x) {
    float r;
    asm("rcp.approx.f32 %0, %1;" : "=f"(r) : "f"(x));
    return r;
}
__device__ __forceinline__ float sigm_f(float x) {
    return rcp_fast(1.f + __expf(-x));
}
// tanh via exp + approx reciprocal; clamp avoids inf/inf. err ~1e-6 rel.
__device__ __forceinline__ float tanh_f(float x) {
    float xx = fminf(fmaxf(x, -15.f), 15.f);
    float e = __expf(2.f * xx);
    return (e - 1.f) * rcp_fast(e + 1.f);
}

// ---------------------------------------------------------------------------
// init: zero h states + barrier counter
// ---------------------------------------------------------------------------
__global__ void init_kernel() {
    int i = blockIdx.x * blockDim.x + threadIdx.x;
    int stride = gridDim.x * blockDim.x;
    for (int j = i; j < 2 * NH * NB + 64; j += stride) { g_h0[j] = 0.f; g_h1[j] = 0.f; }
    if (i == 0) g_bar = 0;
}

// ---------------------------------------------------------------------------
// xg GEMM (layer 0 only): xg[m][n] = emb[tokens] @ Wih0^T + (bih0+bhh0)
// 128x128x8 tile, 256 threads, 8x8 split-column microtile, 2-stage double-
// buffered smem pipeline. min-blocks 2 -> 2 CTAs/SM (regs capped at 128).
// ---------------------------------------------------------------------------
#define XROW 132

__global__ __launch_bounds__(256, 2) void xg_gemm(
    const float* __restrict__ emb,
    const int*   __restrict__ tokens,
    const float* __restrict__ W,        // (2048, 512) row-major
    const float* __restrict__ bih_l,
    const float* __restrict__ bhh_l)
{
    __shared__ float As[2][8 * XROW];
    __shared__ float Bs[2][8 * XROW];
    __shared__ float bias_s[128];

    const int tid = threadIdx.x;
    const int n0 = blockIdx.x * 128;
    const int m0 = blockIdx.y * 128;

    if (tid < 128) bias_s[tid] = bih_l[n0 + tid] + bhh_l[n0 + tid];

    const int lr = tid >> 1;          // 0..127 tile row for loading
    const int kq = (tid & 1) * 4;     // 0 or 4

    const float* arow;
    {
        int m = m0 + lr;
        int t = m >> 5, b = m & 31;
        int tok = tokens[b * NL + t];
        arow = emb + (size_t)tok * 512;
    }
    const float* brow = W + (size_t)(n0 + lr) * 512;

    const int tm  = (tid >> 4) * 8;   // 8 rows
    const int tn4 = (tid & 15) * 4;   // cols tn4..tn4+3 and tn4+64..tn4+67

    unsigned long long acc2[8][4];
#pragma unroll
    for (int i = 0; i < 8; i++)
#pragma unroll
        for (int p = 0; p < 4; p++) acc2[i][p] = 0ull;

    // Prologue: chunk 0 into buffer 0
    {
        float4 av = *(const float4*)(arow + kq);
        float4 bv = *(const float4*)(brow + kq);
        As[0][(kq + 0) * XROW + lr] = av.x; As[0][(kq + 1) * XROW + lr] = av.y;
        As[0][(kq + 2) * XROW + lr] = av.z; As[0][(kq + 3) * XROW + lr] = av.w;
        Bs[0][(kq + 0) * XROW + lr] = bv.x; Bs[0][(kq + 1) * XROW + lr] = bv.y;
        Bs[0][(kq + 2) * XROW + lr] = bv.z; Bs[0][(kq + 3) * XROW + lr] = bv.w;
    }
    __syncthreads();

    int buf = 0;
    for (int k0 = 0; k0 < 512; k0 += 8) {
        float4 av, bv;
        const bool more = (k0 + 8) < 512;
        if (more) {                                   // issue next chunk's loads
            av = *(const float4*)(arow + k0 + 8 + kq);
            bv = *(const float4*)(brow + k0 + 8 + kq);
        }
#pragma unroll
        for (int kk = 0; kk < 8; kk++) {
            float a[8];
            *(float4*)(a)     = *(const float4*)(&As[buf][kk * XROW + tm]);
            *(float4*)(a + 4) = *(const float4*)(&As[buf][kk * XROW + tm + 4]);
            ulonglong2 b01 = *(const ulonglong2*)(&Bs[buf][kk * XROW + tn4]);
            ulonglong2 b23 = *(const ulonglong2*)(&Bs[buf][kk * XROW + tn4 + 64]);
#pragma unroll
            for (int i = 0; i < 8; i++) {
                unsigned long long ad = pack2(a[i]);
                acc2[i][0] = ffma2(ad, b01.x, acc2[i][0]);
                acc2[i][1] = ffma2(ad, b01.y, acc2[i][1]);
                acc2[i][2] = ffma2(ad, b23.x, acc2[i][2]);
                acc2[i][3] = ffma2(ad, b23.y, acc2[i][3]);
            }
        }
        if (more) {                                   // fill other buffer, one sync
            int nb = buf ^ 1;
            As[nb][(kq + 0) * XROW + lr] = av.x; As[nb][(kq + 1) * XROW + lr] = av.y;
            As[nb][(kq + 2) * XROW + lr] = av.z; As[nb][(kq + 3) * XROW + lr] = av.w;
            Bs[nb][(kq + 0) * XROW + lr] = bv.x; Bs[nb][(kq + 1) * XROW + lr] = bv.y;
            Bs[nb][(kq + 2) * XROW + lr] = bv.z; Bs[nb][(kq + 3) * XROW + lr] = bv.w;
            __syncthreads();
            buf = nb;
        }
    }

    ulonglong2 bi01 = *(const ulonglong2*)(&bias_s[tn4]);
    ulonglong2 bi23 = *(const ulonglong2*)(&bias_s[tn4 + 64]);
#pragma unroll
    for (int i = 0; i < 8; i++) {
        float* orow = g_xg + (size_t)(m0 + tm + i) * NG + n0;
        ulonglong2 o0, o1;
        o0.x = addf2(acc2[i][0], bi01.x);
        o0.y = addf2(acc2[i][1], bi01.y);
        o1.x = addf2(acc2[i][2], bi23.x);
        o1.y = addf2(acc2[i][3], bi23.y);
        *(ulonglong2*)(orow + tn4)      = o0;
        *(ulonglong2*)(orow + tn4 + 64) = o1;
    }
}

// ---------------------------------------------------------------------------
// Fused 2-layer pipelined LSTM recurrence (merged-loop schedule).
// 128 CTAs x 512 threads (16 warps). Fused step s (s = 0..512):
//   layer0 computes t=s      (active s<512): gA = Whh0 @ h0[s-1]
//   layer1 computes t=s-1    (active s>=1) : gB = Wih1 @ h0[s-1] + Whh1 @ h1[s-2]
// Warp mapping: warp = rh*8 + kw. kw in 0..7 -> K slice [kw*64,(kw+1)*64);
// rh in 0..1 -> local rows [rh*8, rh*8+8). Lane: rg2 = lane>>3 -> row pair
// (rh*8+rg2*2, +1); bg = lane&7 -> batches bg*4..+3. 12 FFMA2 per k per lane.
// Only 8 partials per output (gate reduce halved vs 16-way k-split).
// Cell state c lives in a REGISTER of its gate thread (persistent).
// ---------------------------------------------------------------------------
#define REDSZ (8 * 16 * 33)   // [kw 0..7][row 0..15] stride-33 padded

__global__ __launch_bounds__(512, 1) void lstm_fused(
    const float* __restrict__ Whh,     // (2, 2048, 512)
    const float* __restrict__ Wih,     // (2, 2048, 512)
    const float* __restrict__ bih,     // (2, 2048)
    const float* __restrict__ bhh,     // (2, 2048)
    float* __restrict__ d_out)
{
    extern __shared__ float sm[];
    float* w0   = sm;                    // 512*16 floats (Whh0 slice, [k][row])
    float* w1i  = w0  + 512 * 16;        // 512*16       (Wih1 slice)
    float* w1h  = w1i + 512 * 16;        // 512*16       (Whh1 slice)
    float* redA = w1h + 512 * 16;        // REDSZ
    float* redB = redA + REDSZ;          // REDSZ

    const int tid = threadIdx.x;
    const int cta = blockIdx.x;          // 0..127 -> units [cta*4, cta*4+4)

    // One-time: load 3 weight slices (16 gate rows each), [k][row] layout
    for (int idx = tid; idx < 3 * 16 * 512; idx += 512) {
        int slice = idx >> 13;           // 0..2
        int rem   = idx & 8191;
        int lrw   = rem >> 9;            // 0..15 (q*4+u)
        int k     = rem & 511;
        int row   = (lrw >> 2) * 512 + cta * 4 + (lrw & 3);
        const float* src = (slice == 0) ? Whh
                         : (slice == 1) ? (Wih + (size_t)NG * NH)
                                        : (Whh + (size_t)NG * NH);
        float v = src[(size_t)row * 512 + k];
        float* dst = (slice == 0) ? w0 : (slice == 1) ? w1i : w1h;
        dst[k * 16 + lrw] = v;
    }
    __syncthreads();

    const int lane = tid & 31, warp = tid >> 5;   // warp 0..15
    const int kw = warp & 7, rh = warp >> 3;      // k-group, row-half
    const int rg2 = lane >> 3, bg = lane & 7;     // row-pair in half, batch grp
    const int k0 = kw * 64;                       // 64-k slice per warp
    const int rowb = rh * 8 + rg2 * 2;            // local row pair base (0..14)

    // Gate-thread constants (tid < 256): set = tid>>7, u = (tid>>5)&3, b = tid&31
    const int gset = tid >> 7, uu = (tid >> 5) & 3, bb = tid & 31;
    int   rowq[4];
    float b1[4];
    float c_reg = 0.f;                   // cell state (layer gset), persistent
    if (tid < 256) {
#pragma unroll
        for (int q = 0; q < 4; q++) {
            rowq[q] = q * 512 + cta * 4 + uu;
            b1[q] = bih[NG + rowq[q]] + bhh[NG + rowq[q]];
        }
    }

    const float* w0b  = w0  + rowb;
    const float* w1ib = w1i + rowb;
    const float* w1hb = w1h + rowb;

    for (int s = 0; s <= NL; s++) {
        // Prefetch layer-0 xg for this step (set-A gate threads)
        float xg0[4];
        if (tid < 128) {
            int t0 = (s < NL) ? s : (NL - 1);
            const float* xp = g_xg + (size_t)(t0 * 32 + bb) * NG;
#pragma unroll
            for (int q = 0; q < 4; q++) xg0[q] = __ldg(xp + rowq[q]);
        }

        // h pointers (previous-step state; buffers alternate)
        const float* h0p = g_h0 + (s & 1) * (NH * NB) + bg * 4;
        const float* h1p = g_h1 + ((s & 1) ^ 1) * (NH * NB) + bg * 4;

        // Merged GEMM with 1-deep h register pipeline.
        // A[j]/Bv[j]: row pair (rowb, rowb+1) for batch bg*4+j.
        unsigned long long A[4], Bv[4];
#pragma unroll
        for (int i = 0; i < 4; i++) { A[i] = 0ull; Bv[i] = 0ull; }

        float4 c0v = *(const float4*)(h0p + k0 * 32);
        float4 c1v = *(const float4*)(h1p + k0 * 32);
#pragma unroll 8
        for (int k = k0; k < k0 + 64; k++) {
            // issue next iteration's loads first (last one overreads into pad)
            float4 n0v = *(const float4*)(h0p + (k + 1) * 32);
            float4 n1v = *(const float4*)(h1p + (k + 1) * 32);

            unsigned long long d00 = pack2(c0v.x), d01 = pack2(c0v.y);
            unsigned long long d02 = pack2(c0v.z), d03 = pack2(c0v.w);
            unsigned long long d10 = pack2(c1v.x), d11 = pack2(c1v.y);
            unsigned long long d12 = pack2(c1v.z), d13 = pack2(c1v.w);

            unsigned long long W0 = *(const unsigned long long*)(w0b + k * 16);
            A[0] = ffma2(W0, d00, A[0]); A[1] = ffma2(W0, d01, A[1]);
            A[2] = ffma2(W0, d02, A[2]); A[3] = ffma2(W0, d03, A[3]);

            unsigned long long W1 = *(const unsigned long long*)(w1ib + k * 16);
            Bv[0] = ffma2(W1, d00, Bv[0]); Bv[1] = ffma2(W1, d01, Bv[1]);
            Bv[2] = ffma2(W1, d02, Bv[2]); Bv[3] = ffma2(W1, d03, Bv[3]);

            unsigned long long W2 = *(const unsigned long long*)(w1hb + k * 16);
            Bv[0] = ffma2(W2, d10, Bv[0]); Bv[1] = ffma2(W2, d11, Bv[1]);
            Bv[2] = ffma2(W2, d12, Bv[2]); Bv[3] = ffma2(W2, d13, Bv[3]);

            c0v = n0v; c1v = n1v;
        }

        // Store partials: pair (p.x, p.y) = rows (rowb, rowb+1), batch bg*4+j
#pragma unroll
        for (int j = 0; j < 4; j++) {
            int b = bg * 4 + j;
            float2 p = unpack2(A[j]);
            redA[(kw * 16 + rowb + 0) * 33 + b] = p.x;
            redA[(kw * 16 + rowb + 1) * 33 + b] = p.y;
            p = unpack2(Bv[j]);
            redB[(kw * 16 + rowb + 0) * 33 + b] = p.x;
            redB[(kw * 16 + rowb + 1) * 33 + b] = p.y;
        }
        __syncthreads();

        // Fused reduce + gates (tid < 256: set A: tid<128 layer0, set B: layer1)
        if (tid < 256) {
            int j = cta * 4 + uu;
            if (gset == 0 && s < NL) {        // layer 0, t = s
                float gq[4];
#pragma unroll
                for (int q = 0; q < 4; q++) {
                    float acc = xg0[q];
                    const float* rp = redA + (q * 4 + uu) * 33 + bb;
#pragma unroll
                    for (int w = 0; w < 8; w++) acc += rp[w * 16 * 33];
                    gq[q] = acc;
                }
                float ig = sigm_f(gq[0]);
                float fg = sigm_f(gq[1]);
                float cg = tanh_f(gq[2]);
                float og = sigm_f(gq[3]);
                float c = fg * c_reg + ig * cg;
                c_reg = c;
                float h = og * tanh_f(c);
                g_h0[((s + 1) & 1) * (NH * NB) + j * 32 + bb] = h;
                if (s == NL - 1) {
                    d_out[bb * NH + j] = h;                               // hidden L0
                    d_out[NLAYERS * NB * NH + bb * NH + j] = c;           // cell  L0
                }
            }
            if (gset == 1 && s >= 1) {        // layer 1, t = s-1
                float gq[4];
#pragma unroll
                for (int q = 0; q < 4; q++) {
                    float acc = b1[q];
                    const float* rp = redB + (q * 4 + uu) * 33 + bb;
#pragma unroll
                    for (int w = 0; w < 8; w++) acc += rp[w * 16 * 33];
                    gq[q] = acc;
                }
                float ig = sigm_f(gq[0]);
                float fg = sigm_f(gq[1]);
                float cg = tanh_f(gq[2]);
                float og = sigm_f(gq[3]);
                float c = fg * c_reg + ig * cg;
                c_reg = c;
                float h = og * tanh_f(c);
                g_h1[(s & 1) * (NH * NB) + j * 32 + bb] = h;
                if (s == NL) {
                    d_out[NB * NH + bb * NH + j] = h;                     // hidden L1
                    d_out[NLAYERS * NB * NH + NB * NH + bb * NH + j] = c; // cell  L1
                }
            }
        }
        __syncthreads();

        // Grid-wide barrier: release-RED arrive (syncthreads above ordered the
        // gate threads' h stores), then acquire-poll. No MEMBAR needed.
        if (s < NL) {
            if (tid == 0) {
                asm volatile("red.release.gpu.global.add.s32 [%0], %1;"
                             :: "l"(&g_bar), "r"(1) : "memory");
                int target = 128 * (s + 1);
                int v;
                do {
                    asm volatile("ld.acquire.gpu.global.s32 %0, [%1];"
                                 : "=r"(v) : "l"(&g_bar) : "memory");
                } while (v < target);
            }
            __syncthreads();
        }
    }
}

// ---------------------------------------------------------------------------
// Launcher
// ---------------------------------------------------------------------------
extern "C" void kernel_launch(void* const* d_in, const int* in_sizes, int n_in,
                              void* d_out, int out_size) {
    const int*   tokens = (const int*)  d_in[0];
    const float* emb    = (const float*)d_in[1];
    const float* Wih    = (const float*)d_in[2];   // (2, 2048, 512)
    const float* Whh    = (const float*)d_in[3];   // (2, 2048, 512)
    const float* bih    = (const float*)d_in[4];   // (2, 2048)
    const float* bhh    = (const float*)d_in[5];   // (2, 2048)
    float* out = (float*)d_out;

    const int FUSED_SMEM = (3 * 512 * 16 + 2 * REDSZ) * 4;   // 132096 B
    cudaFuncSetAttribute(lstm_fused, cudaFuncAttributeMaxDynamicSharedMemorySize,
                         FUSED_SMEM);

    dim3 ggrid(NG / 128, (NL * NB) / 128);   // (16, 128)

    // layer-0 input GEMM (embedding gather fused), then fused 2-layer recurrence
    xg_gemm<<<ggrid, 256>>>(emb, tokens, Wih, bih, bhh);
    init_kernel<<<64, 256>>>();
    lstm_fused<<<128, 512, FUSED_SMEM>>>(Whh, Wih, bih, bhh, out);
}

// round 17
// speedup vs baseline: 1.1997x; 1.1997x over previous
#include <cuda_runtime.h>
#include <cstdint>

// Problem constants
// B=32, L=512, E=H=512, G=4H=2048, N=2 layers, V=32000
#define NB 32
#define NL 512
#define NH 512
#define NG 2048
#define NLAYERS 2

// Scratch (static device globals -- allocation-free).
// h rings padded +64 floats: the k-loop register pipeline prefetches one
// iteration past the slice end (value unused, must not fault).
__device__ float g_xg[(size_t)NL * NB * NG];   // (L*B, 4H) layer-0 gate preacts (input part + bias)
__device__ float g_h0[2 * NH * NB + 64];       // double-buffered h layer0, [buf][j][b]
__device__ float g_h1[2 * NH * NB + 64];       // double-buffered h layer1, [buf][j][b]
__device__ int   g_bar;                        // global barrier counter

// ---------------------------------------------------------------------------
// Packed f32x2 helpers (fma.rn.f32x2 -- 2 fp32 MACs per instruction)
// ---------------------------------------------------------------------------
__device__ __forceinline__ unsigned long long ffma2(unsigned long long a,
                                                    unsigned long long b,
                                                    unsigned long long c) {
    unsigned long long d;
    asm("fma.rn.f32x2 %0, %1, %2, %3;" : "=l"(d) : "l"(a), "l"(b), "l"(c));
    return d;
}
__device__ __forceinline__ unsigned long long addf2(unsigned long long a,
                                                    unsigned long long b) {
    unsigned long long d;
    asm("add.rn.f32x2 %0, %1, %2;" : "=l"(d) : "l"(a), "l"(b));
    return d;
}
__device__ __forceinline__ unsigned long long pack2(float x) {
    unsigned long long d;
    asm("mov.b64 %0, {%1, %1};" : "=l"(d) : "f"(x));
    return d;
}
__device__ __forceinline__ float2 unpack2(unsigned long long u) {
    float2 f;
    asm("mov.b64 {%0, %1}, %2;" : "=f"(f.x), "=f"(f.y) : "l"(u));
    return f;
}

__device__ __forceinline__ float rcp_fast(float x) {
    float r;
    asm("rcp.approx.f32 %0, %1;" : "=f"(r) : "f"(x));
    return r;
}
__device__ __forceinline__ float sigm_f(float x) {
    return rcp_fast(1.f + __expf(-x));
}
// tanh via exp + approx reciprocal; clamp avoids inf/inf. err ~1e-6 rel.
__device__ __forceinline__ float tanh_f(float x) {
    float xx = fminf(fmaxf(x, -15.f), 15.f);
    float e = __expf(2.f * xx);
    return (e - 1.f) * rcp_fast(e + 1.f);
}

// ---------------------------------------------------------------------------
// init: zero h states + barrier counter
// ---------------------------------------------------------------------------
__global__ void init_kernel() {
    int i = blockIdx.x * blockDim.x + threadIdx.x;
    int stride = gridDim.x * blockDim.x;
    for (int j = i; j < 2 * NH * NB + 64; j += stride) { g_h0[j] = 0.f; g_h1[j] = 0.f; }
    if (i == 0) g_bar = 0;
}

// ---------------------------------------------------------------------------
// xg GEMM (layer 0 only): xg[m][n] = emb[tokens] @ Wih0^T + (bih0+bhh0)
// 128x128x8 tile, 256 threads, 8x8 split-column microtile, 2-stage double-
// buffered smem pipeline, 2 CTAs/SM.
// ---------------------------------------------------------------------------
#define XROW 132

__global__ __launch_bounds__(256, 2) void xg_gemm(
    const float* __restrict__ emb,
    const int*   __restrict__ tokens,
    const float* __restrict__ W,        // (2048, 512) row-major
    const float* __restrict__ bih_l,
    const float* __restrict__ bhh_l)
{
    __shared__ float As[2][8 * XROW];
    __shared__ float Bs[2][8 * XROW];
    __shared__ float bias_s[128];

    const int tid = threadIdx.x;
    const int n0 = blockIdx.x * 128;
    const int m0 = blockIdx.y * 128;

    if (tid < 128) bias_s[tid] = bih_l[n0 + tid] + bhh_l[n0 + tid];

    const int lr = tid >> 1;          // 0..127 tile row for loading
    const int kq = (tid & 1) * 4;     // 0 or 4

    const float* arow;
    {
        int m = m0 + lr;
        int t = m >> 5, b = m & 31;
        int tok = tokens[b * NL + t];
        arow = emb + (size_t)tok * 512;
    }
    const float* brow = W + (size_t)(n0 + lr) * 512;

    const int tm  = (tid >> 4) * 8;   // 8 rows
    const int tn4 = (tid & 15) * 4;   // cols tn4..tn4+3 and tn4+64..tn4+67

    unsigned long long acc2[8][4];
#pragma unroll
    for (int i = 0; i < 8; i++)
#pragma unroll
        for (int p = 0; p < 4; p++) acc2[i][p] = 0ull;

    // Prologue: chunk 0 into buffer 0
    {
        float4 av = *(const float4*)(arow + kq);
        float4 bv = *(const float4*)(brow + kq);
        As[0][(kq + 0) * XROW + lr] = av.x; As[0][(kq + 1) * XROW + lr] = av.y;
        As[0][(kq + 2) * XROW + lr] = av.z; As[0][(kq + 3) * XROW + lr] = av.w;
        Bs[0][(kq + 0) * XROW + lr] = bv.x; Bs[0][(kq + 1) * XROW + lr] = bv.y;
        Bs[0][(kq + 2) * XROW + lr] = bv.z; Bs[0][(kq + 3) * XROW + lr] = bv.w;
    }
    __syncthreads();

    int buf = 0;
    for (int k0 = 0; k0 < 512; k0 += 8) {
        float4 av, bv;
        const bool more = (k0 + 8) < 512;
        if (more) {                                   // issue next chunk's loads
            av = *(const float4*)(arow + k0 + 8 + kq);
            bv = *(const float4*)(brow + k0 + 8 + kq);
        }
#pragma unroll
        for (int kk = 0; kk < 8; kk++) {
            float a[8];
            *(float4*)(a)     = *(const float4*)(&As[buf][kk * XROW + tm]);
            *(float4*)(a + 4) = *(const float4*)(&As[buf][kk * XROW + tm + 4]);
            ulonglong2 b01 = *(const ulonglong2*)(&Bs[buf][kk * XROW + tn4]);
            ulonglong2 b23 = *(const ulonglong2*)(&Bs[buf][kk * XROW + tn4 + 64]);
#pragma unroll
            for (int i = 0; i < 8; i++) {
                unsigned long long ad = pack2(a[i]);
                acc2[i][0] = ffma2(ad, b01.x, acc2[i][0]);
                acc2[i][1] = ffma2(ad, b01.y, acc2[i][1]);
                acc2[i][2] = ffma2(ad, b23.x, acc2[i][2]);
                acc2[i][3] = ffma2(ad, b23.y, acc2[i][3]);
            }
        }
        if (more) {                                   // fill other buffer, one sync
            int nb = buf ^ 1;
            As[nb][(kq + 0) * XROW + lr] = av.x; As[nb][(kq + 1) * XROW + lr] = av.y;
            As[nb][(kq + 2) * XROW + lr] = av.z; As[nb][(kq + 3) * XROW + lr] = av.w;
            Bs[nb][(kq + 0) * XROW + lr] = bv.x; Bs[nb][(kq + 1) * XROW + lr] = bv.y;
            Bs[nb][(kq + 2) * XROW + lr] = bv.z; Bs[nb][(kq + 3) * XROW + lr] = bv.w;
            __syncthreads();
            buf = nb;
        }
    }

    ulonglong2 bi01 = *(const ulonglong2*)(&bias_s[tn4]);
    ulonglong2 bi23 = *(const ulonglong2*)(&bias_s[tn4 + 64]);
#pragma unroll
    for (int i = 0; i < 8; i++) {
        float* orow = g_xg + (size_t)(m0 + tm + i) * NG + n0;
        ulonglong2 o0, o1;
        o0.x = addf2(acc2[i][0], bi01.x);
        o0.y = addf2(acc2[i][1], bi01.y);
        o1.x = addf2(acc2[i][2], bi23.x);
        o1.y = addf2(acc2[i][3], bi23.y);
        *(ulonglong2*)(orow + tn4)      = o0;
        *(ulonglong2*)(orow + tn4 + 64) = o1;
    }
}

// ---------------------------------------------------------------------------
// Fused 2-layer pipelined LSTM recurrence (validated R15 merged-loop mapping).
// 128 CTAs x 512 threads (16 warps). Fused step s (s = 0..512):
//   layer0 computes t=s      (active s<512): gA = Whh0 @ h0[s-1]
//   layer1 computes t=s-1    (active s>=1) : gB = Wih1 @ h0[s-1] + Whh1 @ h1[s-2]
// K split 16 ways (32 k per warp, each h element loaded ONCE per CTA).
// Weights non-duplicated in smem, FFMA2 row-paired, 24 FFMA2 per k.
// 1-deep h register pipeline. Cell state in a register of its gate thread.
// ---------------------------------------------------------------------------
#define REDSZ (16 * 16 * 33)   // [warp 0..15][row 0..15] stride-33 padded

__global__ __launch_bounds__(512, 1) void lstm_fused(
    const float* __restrict__ Whh,     // (2, 2048, 512)
    const float* __restrict__ Wih,     // (2, 2048, 512)
    const float* __restrict__ bih,     // (2, 2048)
    const float* __restrict__ bhh,     // (2, 2048)
    float* __restrict__ d_out)
{
    extern __shared__ float sm[];
    float* w0   = sm;                    // 512*16 floats (Whh0 slice, [k][row])
    float* w1i  = w0  + 512 * 16;        // 512*16       (Wih1 slice)
    float* w1h  = w1i + 512 * 16;        // 512*16       (Whh1 slice)
    float* redA = w1h + 512 * 16;        // REDSZ
    float* redB = redA + REDSZ;          // REDSZ

    const int tid = threadIdx.x;
    const int cta = blockIdx.x;          // 0..127 -> units [cta*4, cta*4+4)

    // One-time: load 3 weight slices (16 gate rows each), [k][row] layout
    for (int idx = tid; idx < 3 * 16 * 512; idx += 512) {
        int slice = idx >> 13;           // 0..2
        int rem   = idx & 8191;
        int lrw   = rem >> 9;            // 0..15 (q*4+u)
        int k     = rem & 511;
        int row   = (lrw >> 2) * 512 + cta * 4 + (lrw & 3);
        const float* src = (slice == 0) ? Whh
                         : (slice == 1) ? (Wih + (size_t)NG * NH)
                                        : (Whh + (size_t)NG * NH);
        float v = src[(size_t)row * 512 + k];
        float* dst = (slice == 0) ? w0 : (slice == 1) ? w1i : w1h;
        dst[k * 16 + lrw] = v;
    }
    __syncthreads();

    const int lane = tid & 31, warp = tid >> 5;   // warp 0..15
    const int rg = lane >> 3, bg = lane & 7;      // rg: 4 rows, bg: 4 batch
    const int k0 = warp * 32;                     // 32-k slice per warp

    // Gate-thread constants (tid < 256): set = tid>>7, u = (tid>>5)&3, b = tid&31
    const int gset = tid >> 7, uu = (tid >> 5) & 3, bb = tid & 31;
    int   rowq[4];
    float b1[4];
    float c_reg = 0.f;                   // cell state (layer gset), persistent
    if (tid < 256) {
#pragma unroll
        for (int q = 0; q < 4; q++) {
            rowq[q] = q * 512 + cta * 4 + uu;
            b1[q] = bih[NG + rowq[q]] + bhh[NG + rowq[q]];
        }
    }

    const float* w0b  = w0  + rg * 4;
    const float* w1ib = w1i + rg * 4;
    const float* w1hb = w1h + rg * 4;

    for (int s = 0; s <= NL; s++) {
        // Prefetch layer-0 xg for this step (set-A gate threads)
        float xg0[4];
        if (tid < 128) {
            int t0 = (s < NL) ? s : (NL - 1);
            const float* xp = g_xg + (size_t)(t0 * 32 + bb) * NG;
#pragma unroll
            for (int q = 0; q < 4; q++) xg0[q] = __ldg(xp + rowq[q]);
        }

        // h pointers (previous-step state; buffers alternate)
        const float* h0p = g_h0 + (s & 1) * (NH * NB) + bg * 4;
        const float* h1p = g_h1 + ((s & 1) ^ 1) * (NH * NB) + bg * 4;

        // Merged GEMM with explicit 1-deep h register pipeline.
        unsigned long long A[8], Bv[8];
#pragma unroll
        for (int i = 0; i < 8; i++) { A[i] = 0ull; Bv[i] = 0ull; }

        float4 c0v = *(const float4*)(h0p + k0 * 32);
        float4 c1v = *(const float4*)(h1p + k0 * 32);
#pragma unroll 8
        for (int k = k0; k < k0 + 32; k++) {
            // issue next iteration's loads first (last one overreads into pad)
            float4 n0v = *(const float4*)(h0p + (k + 1) * 32);
            float4 n1v = *(const float4*)(h1p + (k + 1) * 32);

            unsigned long long d00 = pack2(c0v.x), d01 = pack2(c0v.y);
            unsigned long long d02 = pack2(c0v.z), d03 = pack2(c0v.w);
            unsigned long long d10 = pack2(c1v.x), d11 = pack2(c1v.y);
            unsigned long long d12 = pack2(c1v.z), d13 = pack2(c1v.w);

            ulonglong2 W0 = *(const ulonglong2*)(w0b + k * 16);
            A[0] = ffma2(W0.x, d00, A[0]); A[1] = ffma2(W0.x, d01, A[1]);
            A[2] = ffma2(W0.x, d02, A[2]); A[3] = ffma2(W0.x, d03, A[3]);
            A[4] = ffma2(W0.y, d00, A[4]); A[5] = ffma2(W0.y, d01, A[5]);
            A[6] = ffma2(W0.y, d02, A[6]); A[7] = ffma2(W0.y, d03, A[7]);

            ulonglong2 W1 = *(const ulonglong2*)(w1ib + k * 16);
            Bv[0] = ffma2(W1.x, d00, Bv[0]); Bv[1] = ffma2(W1.x, d01, Bv[1]);
            Bv[2] = ffma2(W1.x, d02, Bv[2]); Bv[3] = ffma2(W1.x, d03, Bv[3]);
            Bv[4] = ffma2(W1.y, d00, Bv[4]); Bv[5] = ffma2(W1.y, d01, Bv[5]);
            Bv[6] = ffma2(W1.y, d02, Bv[6]); Bv[7] = ffma2(W1.y, d03, Bv[7]);

            ulonglong2 W2 = *(const ulonglong2*)(w1hb + k * 16);
            Bv[0] = ffma2(W2.x, d10, Bv[0]); Bv[1] = ffma2(W2.x, d11, Bv[1]);
            Bv[2] = ffma2(W2.x, d12, Bv[2]); Bv[3] = ffma2(W2.x, d13, Bv[3]);
            Bv[4] = ffma2(W2.y, d10, Bv[4]); Bv[5] = ffma2(W2.y, d11, Bv[5]);
            Bv[6] = ffma2(W2.y, d12, Bv[6]); Bv[7] = ffma2(W2.y, d13, Bv[7]);

            c0v = n0v; c1v = n1v;
        }

        // Store partials: pair (p.x, p.y) = rows (rg*4+rp*2, +1), batch bg*4+j
#pragma unroll
        for (int rp = 0; rp < 2; rp++)
#pragma unroll
            for (int j = 0; j < 4; j++) {
                int b = bg * 4 + j;
                int r = rg * 4 + rp * 2;
                float2 p = unpack2(A[rp * 4 + j]);
                redA[(warp * 16 + r + 0) * 33 + b] = p.x;
                redA[(warp * 16 + r + 1) * 33 + b] = p.y;
                p = unpack2(Bv[rp * 4 + j]);
                redB[(warp * 16 + r + 0) * 33 + b] = p.x;
                redB[(warp * 16 + r + 1) * 33 + b] = p.y;
            }
        __syncthreads();

        // Fused reduce + gates (tid < 256: set A: tid<128 layer0, set B: layer1)
        if (tid < 256) {
            int j = cta * 4 + uu;
            if (gset == 0 && s < NL) {        // layer 0, t = s
                float gq[4];
#pragma unroll
                for (int q = 0; q < 4; q++) {
                    float acc = xg0[q];
                    const float* rp = redA + (q * 4 + uu) * 33 + bb;
#pragma unroll
                    for (int w = 0; w < 16; w++) acc += rp[w * 16 * 33];
                    gq[q] = acc;
                }
                float ig = sigm_f(gq[0]);
                float fg = sigm_f(gq[1]);
                float cg = tanh_f(gq[2]);
                float og = sigm_f(gq[3]);
                float c = fg * c_reg + ig * cg;
                c_reg = c;
                float h = og * tanh_f(c);
                g_h0[((s + 1) & 1) * (NH * NB) + j * 32 + bb] = h;
                if (s == NL - 1) {
                    d_out[bb * NH + j] = h;                               // hidden L0
                    d_out[NLAYERS * NB * NH + bb * NH + j] = c;           // cell  L0
                }
            }
            if (gset == 1 && s >= 1) {        // layer 1, t = s-1
                float gq[4];
#pragma unroll
                for (int q = 0; q < 4; q++) {
                    float acc = b1[q];
                    const float* rp = redB + (q * 4 + uu) * 33 + bb;
#pragma unroll
                    for (int w = 0; w < 16; w++) acc += rp[w * 16 * 33];
                    gq[q] = acc;
                }
                float ig = sigm_f(gq[0]);
                float fg = sigm_f(gq[1]);
                float cg = tanh_f(gq[2]);
                float og = sigm_f(gq[3]);
                float c = fg * c_reg + ig * cg;
                c_reg = c;
                float h = og * tanh_f(c);
                g_h1[(s & 1) * (NH * NB) + j * 32 + bb] = h;
                if (s == NL) {
                    d_out[NB * NH + bb * NH + j] = h;                     // hidden L1
                    d_out[NLAYERS * NB * NH + NB * NH + bb * NH + j] = c; // cell  L1
                }
            }
        }
        __syncthreads();

        // Grid-wide barrier: release-RED arrive (syncthreads above ordered the
        // gate threads' h stores), then acquire-poll. No MEMBAR needed.
        if (s < NL) {
            if (tid == 0) {
                asm volatile("red.release.gpu.global.add.s32 [%0], %1;"
                             :: "l"(&g_bar), "r"(1) : "memory");
                int target = 128 * (s + 1);
                int v;
                do {
                    asm volatile("ld.acquire.gpu.global.s32 %0, [%1];"
                                 : "=r"(v) : "l"(&g_bar) : "memory");
                } while (v < target);
            }
            __syncthreads();
        }
    }
}

// ---------------------------------------------------------------------------
// Launcher
// ---------------------------------------------------------------------------
extern "C" void kernel_launch(void* const* d_in, const int* in_sizes, int n_in,
                              void* d_out, int out_size) {
    const int*   tokens = (const int*)  d_in[0];
    const float* emb    = (const float*)d_in[1];
    const float* Wih    = (const float*)d_in[2];   // (2, 2048, 512)
    const float* Whh    = (const float*)d_in[3];   // (2, 2048, 512)
    const float* bih    = (const float*)d_in[4];   // (2, 2048)
    const float* bhh    = (const float*)d_in[5];   // (2, 2048)
    float* out = (float*)d_out;

    const int FUSED_SMEM = (3 * 512 * 16 + 2 * REDSZ) * 4;   // 165888 B
    cudaFuncSetAttribute(lstm_fused, cudaFuncAttributeMaxDynamicSharedMemorySize,
                         FUSED_SMEM);

    dim3 ggrid(NG / 128, (NL * NB) / 128);   // (16, 128)

    // layer-0 input GEMM (embedding gather fused), then fused 2-layer recurrence
    xg_gemm<<<ggrid, 256>>>(emb, tokens, Wih, bih, bhh);
    init_kernel<<<64, 256>>>();
    lstm_fused<<<128, 512, FUSED_SMEM>>>(Whh, Wih, bih, bhh, out);
}